// round 7
// baseline (speedup 1.0000x reference)
#include <cuda_runtime.h>
#include <cstdint>

// Problem constants (fixed by setup_inputs: index = 256)
#define B      64
#define S      512
#define D      768
#define H      12
#define TOPK   254          // index - 2
#define NKEEP  255          // index - 1 (top + CLS)
#define NOTHER 257          // S - index + 1
#define D4     (D / 4)      // 192 float4 per row

// -------- scratch (no allocation allowed -> __device__ globals) --------
__device__ float g_part[B * H * S];     // per-(b,h) column sums minus diag
__device__ int   g_rowsrc[B * NKEEP];   // source token index for each kept output row
__device__ int   g_osrc[B * NOTHER];    // source token index for "other" set
__device__ float g_ow[B * NOTHER];      // softmax weight / NOTHER for "other" set

// ============================================================
// K1: column sums minus diagonal, per (b, h) plane.
// grid = B*H blocks, 512 threads; thread j accumulates column j.
// Each unrolled load instruction covers a full contiguous 2KB row -> perfectly
// coalesced HBM streaming; 8 independent accumulators for MLP.
// ============================================================
__global__ __launch_bounds__(512) void colsum_kernel(const float* __restrict__ atten) {
    const int bh = blockIdx.x;
    const int j  = threadIdx.x;
    const float* A = atten + (size_t)bh * S * S;

    float a0 = 0.f, a1 = 0.f, a2 = 0.f, a3 = 0.f;
    float a4 = 0.f, a5 = 0.f, a6 = 0.f, a7 = 0.f;
    for (int i = 0; i < S; i += 8) {
        a0 += A[(i + 0) * S + j];
        a1 += A[(i + 1) * S + j];
        a2 += A[(i + 2) * S + j];
        a3 += A[(i + 3) * S + j];
        a4 += A[(i + 4) * S + j];
        a5 += A[(i + 5) * S + j];
        a6 += A[(i + 6) * S + j];
        a7 += A[(i + 7) * S + j];
    }
    float s = ((a0 + a1) + (a2 + a3)) + ((a4 + a5) + (a6 + a7));
    s -= A[j * S + j];           // subtract diagonal (j,j) of this head
    g_part[bh * S + j] = s;
}

// ============================================================
// K2: per-batch selection.
//  - reduce 12 head partials -> ab[t] for token t+1 (t in 0..510)
//  - exact rank with jax top_k tie-break (lower index first)
//  - prefix scan -> compact keep rows (sorted ascending: CLS=0 then ascending
//    token idx, which IS jnp.sort(concat(top_idx, 0)))
//  - softmax weights over the complementary 257-element "other" set
// grid = B blocks, 512 threads.
// ============================================================
__global__ __launch_bounds__(512) void select_kernel() {
    __shared__ float v[512];
    __shared__ int   scan[512];
    __shared__ float red[512];

    const int b = blockIdx.x;
    const int t = threadIdx.x;          // token index = t + 1

    float val = -3.0e38f;
    if (t < S - 1) {
        float s = 0.f;
        #pragma unroll
        for (int h = 0; h < H; h++)
            s += g_part[(b * H + h) * S + (t + 1)];
        val = s * (1.0f / (float)H);
    }
    v[t] = val;
    __syncthreads();

    // exact rank (O(n) per thread, broadcast smem reads)
    int r = 0;
    if (t < S - 1) {
        const float mv = val;
        for (int k = 0; k < S - 1; k++) {
            float vk = v[k];
            r += (vk > mv) || (vk == mv && k < t);
        }
    }
    const int flag = (t < S - 1 && r < TOPK) ? 1 : 0;   // in top set?

    // inclusive Hillis-Steele scan of flags over 512 slots
    scan[t] = flag;
    __syncthreads();
    for (int off = 1; off < 512; off <<= 1) {
        int x = scan[t];
        int y = (t >= off) ? scan[t - off] : 0;
        __syncthreads();
        scan[t] = x + y;
        __syncthreads();
    }
    const int excl = scan[t] - flag;     // #top-set tokens with index < t

    // softmax over the "other" set: max then sum
    red[t] = (t < S - 1 && !flag) ? val : -3.0e38f;
    __syncthreads();
    for (int off = 256; off > 0; off >>= 1) {
        if (t < off) red[t] = fmaxf(red[t], red[t + off]);
        __syncthreads();
    }
    const float m = red[0];
    __syncthreads();

    const float e = (t < S - 1 && !flag) ? expf(val - m) : 0.f;
    red[t] = e;
    __syncthreads();
    for (int off = 256; off > 0; off >>= 1) {
        if (t < off) red[t] += red[t + off];
        __syncthreads();
    }
    const float Z = red[0];

    if (t < S - 1) {
        if (flag) {
            g_rowsrc[b * NKEEP + 1 + excl] = t + 1;     // slots 1..254, ascending
        } else {
            int p = t - excl;                            // #other tokens with index < t
            g_osrc[b * NOTHER + p] = t + 1;
            g_ow[b * NOTHER + p]   = e / (Z * (float)NOTHER);  // softmax * (1/mean-count)
        }
    }
    if (t == S - 1) g_rowsrc[b * NKEEP] = 0;             // CLS token
}

// ============================================================
// K3: output assembly. grid = (256, B), 192 threads, float4 rows.
// blockIdx.x == 0  -> weighted-mean row (out row 255); launched FIRST since
//                     it's the latency tail (257 scattered 3KB row reads).
// blockIdx.x >= 1  -> copy kept row (blockIdx.x - 1).
// ============================================================
__global__ __launch_bounds__(192) void gather_kernel(const float4* __restrict__ x4,
                                                     float4* __restrict__ out4) {
    const int b = blockIdx.y;
    const int t = threadIdx.x;
    const float4* xb = x4  + (size_t)b * S   * D4;
    float4*       ob = out4 + (size_t)b * 256 * D4;

    if (blockIdx.x != 0) {
        const int r   = blockIdx.x - 1;                  // 0..254
        const int src = g_rowsrc[b * NKEEP + r];
        ob[r * D4 + t] = xb[src * D4 + t];
    } else {
        __shared__ float sw[NOTHER];
        __shared__ int   ss[NOTHER];
        for (int q = t; q < NOTHER; q += 192) {
            sw[q] = g_ow[b * NOTHER + q];
            ss[q] = g_osrc[b * NOTHER + q];
        }
        __syncthreads();
        float4 acc = make_float4(0.f, 0.f, 0.f, 0.f);
        #pragma unroll 8
        for (int q = 0; q < NOTHER; q++) {
            const float  w  = sw[q];
            const float4 xv = xb[ss[q] * D4 + t];
            acc.x += w * xv.x;
            acc.y += w * xv.y;
            acc.z += w * xv.z;
            acc.w += w * xv.w;
        }
        ob[255 * D4 + t] = acc;
    }
}

extern "C" void kernel_launch(void* const* d_in, const int* in_sizes, int n_in,
                              void* d_out, int out_size) {
    const float* x     = (const float*)d_in[0];   // (64, 512, 768) f32
    const float* atten = (const float*)d_in[1];   // (768, 512, 512) f32
    // d_in[2] = index (int32, == 256) -- baked into compile-time constants

    colsum_kernel<<<B * H, 512>>>(atten);
    select_kernel<<<B, 512>>>();
    gather_kernel<<<dim3(256, B), 192>>>((const float4*)x, (float4*)d_out);
}

// round 8
// speedup vs baseline: 1.0467x; 1.0467x over previous
#include <cuda_runtime.h>
#include <cstdint>

// Problem constants (fixed by setup_inputs: index = 256)
#define B      64
#define S      512
#define D      768
#define H      12
#define TOPK   254          // index - 2
#define NKEEP  255          // index - 1 (top + CLS)
#define NOTHER 257          // S - index + 1
#define D4     (D / 4)      // 192 float4 per row
#define S4     (S / 4)      // 128 float4 per atten row

// -------- scratch (no allocation allowed -> __device__ globals) --------
__device__ __align__(16) float g_part[B * H * S]; // per-(b,h) column sums minus diag
__device__ int   g_rowsrc[B * NKEEP];   // source token index per kept output row
__device__ int   g_osrc[B * NOTHER];    // source token index for "other" set
__device__ float g_ow[B * NOTHER];      // softmax weight / NOTHER for "other" set
__device__ int   g_cnt[B];              // per-batch head-completion counter (self-resetting)

// ============================================================
// K1 (fused): column sums minus diagonal per (b,h) plane, float4 streaming.
// grid = B*H = 768 blocks, 512 threads.
//   thread t: seg = t>>7 (row range seg*128..+127), q = t&127 (float4 col group)
//   4 independent float4 accumulators -> 64B of LDG.128 in flight per thread.
// After writing its plane, each block bumps g_cnt[b]; the 12th block for a
// batch runs the full selection (rank / scan / softmax) for that batch and
// resets the counter (deterministic across graph replays).
// ============================================================
__global__ __launch_bounds__(512) void colsum_select_kernel(const float* __restrict__ atten) {
    __shared__ float4 s4[4][128];
    __shared__ float  sd[512];
    __shared__ int    s_old;
    // selection-phase smem
    __shared__ float v[512];
    __shared__ int   scan[512];
    __shared__ float red[512];

    const int bh = blockIdx.x;
    const int b  = bh / H;
    const int t  = threadIdx.x;
    const float* A = atten + (size_t)bh * S * S;

    // ---- phase 1: plane column-sum (vectorized) ----
    {
        const int q   = t & 127;
        const int seg = t >> 7;
        const float4* A4 = (const float4*)A;
        const float4* Ar = A4 + (size_t)(seg * 128) * S4 + q;

        float4 c0 = make_float4(0.f, 0.f, 0.f, 0.f);
        float4 c1 = make_float4(0.f, 0.f, 0.f, 0.f);
        float4 c2 = make_float4(0.f, 0.f, 0.f, 0.f);
        float4 c3 = make_float4(0.f, 0.f, 0.f, 0.f);
        #pragma unroll 4
        for (int i = 0; i < 128; i += 4) {
            float4 x0 = Ar[(i + 0) * S4];
            float4 x1 = Ar[(i + 1) * S4];
            float4 x2 = Ar[(i + 2) * S4];
            float4 x3 = Ar[(i + 3) * S4];
            c0.x += x0.x; c0.y += x0.y; c0.z += x0.z; c0.w += x0.w;
            c1.x += x1.x; c1.y += x1.y; c1.z += x1.z; c1.w += x1.w;
            c2.x += x2.x; c2.y += x2.y; c2.z += x2.z; c2.w += x2.w;
            c3.x += x3.x; c3.y += x3.y; c3.z += x3.z; c3.w += x3.w;
        }
        float4 cc;
        cc.x = (c0.x + c1.x) + (c2.x + c3.x);
        cc.y = (c0.y + c1.y) + (c2.y + c3.y);
        cc.z = (c0.z + c1.z) + (c2.z + c3.z);
        cc.w = (c0.w + c1.w) + (c2.w + c3.w);
        s4[seg][q] = cc;
        sd[t] = A[(size_t)t * S + t];           // diagonal element j = t
        __syncthreads();

        if (t < 128) {
            float4 a = s4[0][t], bb = s4[1][t], c = s4[2][t], d = s4[3][t];
            float4 tot;
            tot.x = (a.x + bb.x) + (c.x + d.x) - sd[4 * t + 0];
            tot.y = (a.y + bb.y) + (c.y + d.y) - sd[4 * t + 1];
            tot.z = (a.z + bb.z) + (c.z + d.z) - sd[4 * t + 2];
            tot.w = (a.w + bb.w) + (c.w + d.w) - sd[4 * t + 3];
            ((float4*)g_part)[(size_t)bh * 128 + t] = tot;
        }
    }

    // ---- completion handshake ----
    __threadfence();                            // release: g_part visible device-wide
    if (t == 0) s_old = atomicAdd(&g_cnt[b], 1);
    __syncthreads();
    if (s_old != H - 1) return;                 // not the last head for this batch
    __threadfence();                            // acquire: see all heads' g_part

    // ---- phase 2: selection for batch b (verbatim from passing kernel) ----
    float val = -3.0e38f;
    if (t < S - 1) {
        float s = 0.f;
        #pragma unroll
        for (int h = 0; h < H; h++)
            s += g_part[(b * H + h) * S + (t + 1)];
        val = s * (1.0f / (float)H);
    }
    v[t] = val;
    __syncthreads();

    // exact rank with jax top_k tie-break (lower index first)
    int r = 0;
    if (t < S - 1) {
        const float mv = val;
        for (int k = 0; k < S - 1; k++) {
            float vk = v[k];
            r += (vk > mv) || (vk == mv && k < t);
        }
    }
    const int flag = (t < S - 1 && r < TOPK) ? 1 : 0;

    // inclusive Hillis-Steele scan of flags
    scan[t] = flag;
    __syncthreads();
    for (int off = 1; off < 512; off <<= 1) {
        int x = scan[t];
        int y = (t >= off) ? scan[t - off] : 0;
        __syncthreads();
        scan[t] = x + y;
        __syncthreads();
    }
    const int excl = scan[t] - flag;

    // softmax over the "other" set: max then sum
    red[t] = (t < S - 1 && !flag) ? val : -3.0e38f;
    __syncthreads();
    for (int off = 256; off > 0; off >>= 1) {
        if (t < off) red[t] = fmaxf(red[t], red[t + off]);
        __syncthreads();
    }
    const float m = red[0];
    __syncthreads();

    const float e = (t < S - 1 && !flag) ? expf(val - m) : 0.f;
    red[t] = e;
    __syncthreads();
    for (int off = 256; off > 0; off >>= 1) {
        if (t < off) red[t] += red[t + off];
        __syncthreads();
    }
    const float Z = red[0];

    if (t < S - 1) {
        if (flag) {
            g_rowsrc[b * NKEEP + 1 + excl] = t + 1;       // slots 1..254, ascending
        } else {
            int p = t - excl;
            g_osrc[b * NOTHER + p] = t + 1;
            g_ow[b * NOTHER + p]   = e / (Z * (float)NOTHER);
        }
    }
    if (t == S - 1) g_rowsrc[b * NKEEP] = 0;              // CLS token
    if (t == 0)     g_cnt[b] = 0;                         // reset for next replay
}

// ============================================================
// K2: output assembly. grid = (9, B), 256 threads.
//   blockIdx.x == 0   -> weighted-mean row (out row 255)
//   blockIdx.x = 1..8 -> 32 kept rows each (last chunk: 31), flat float4 copy
//                        with smem-cached source indices.
// ============================================================
__global__ __launch_bounds__(256) void gather_kernel(const float4* __restrict__ x4,
                                                     float4* __restrict__ out4) {
    const int b = blockIdx.y;
    const int t = threadIdx.x;
    const float4* xb = x4   + (size_t)b * S   * D4;
    float4*       ob = out4 + (size_t)b * 256 * D4;

    if (blockIdx.x == 0) {
        // weighted mean of the 257 "other" rows
        __shared__ float sw[NOTHER];
        __shared__ int   ss[NOTHER];
        for (int q = t; q < NOTHER; q += 256) {
            sw[q] = g_ow[b * NOTHER + q];
            ss[q] = g_osrc[b * NOTHER + q];
        }
        __syncthreads();
        if (t < D4) {
            float4 acc = make_float4(0.f, 0.f, 0.f, 0.f);
            #pragma unroll 8
            for (int q = 0; q < NOTHER; q++) {
                const float  w  = sw[q];
                const float4 xv = xb[ss[q] * D4 + t];
                acc.x += w * xv.x;
                acc.y += w * xv.y;
                acc.z += w * xv.z;
                acc.w += w * xv.w;
            }
            ob[255 * D4 + t] = acc;
        }
    } else {
        const int base  = (blockIdx.x - 1) * 32;           // first output row
        const int nrows = (base + 32 <= NKEEP) ? 32 : (NKEEP - base);
        __shared__ int ssrc[32];
        if (t < nrows) ssrc[t] = g_rowsrc[b * NKEEP + base + t];
        __syncthreads();
        const int n = nrows * D4;
        for (int i = t; i < n; i += 256) {
            const int row = i / D4;
            const int col = i - row * D4;
            ob[(base + row) * D4 + col] = xb[ssrc[row] * D4 + col];
        }
    }
}

extern "C" void kernel_launch(void* const* d_in, const int* in_sizes, int n_in,
                              void* d_out, int out_size) {
    const float* x     = (const float*)d_in[0];   // (64, 512, 768) f32
    const float* atten = (const float*)d_in[1];   // (768, 512, 512) f32
    // d_in[2] = index (int32, == 256) -- baked into compile-time constants

    colsum_select_kernel<<<B * H, 512>>>(atten);
    gather_kernel<<<dim3(9, B), 256>>>((const float4*)x, (float4*)d_out);
}

// round 10
// speedup vs baseline: 1.2476x; 1.1919x over previous
#include <cuda_runtime.h>
#include <cstdint>

// Problem constants (fixed by setup_inputs: index = 256)
#define B      64
#define S      512
#define D      768
#define H      12
#define TOPK   254          // index - 2
#define NKEEP  255          // index - 1 (top + CLS)
#define NOTHER 257          // S - index + 1
#define D4     (D / 4)      // 192 float4 per row
#define S4     (S / 4)      // 128 float4 per atten row

#define NCOPY_ELEM (B * NKEEP * D4)      // 3,133,440 float4
#define GATHER_THREADS 768
#define NCOPY_BLOCKS (NCOPY_ELEM / GATHER_THREADS)   // 4080 exactly

// -------- scratch (no allocation allowed -> __device__ globals) --------
__device__ __align__(16) float g_part[B * H * S]; // per-(b,h) column sums minus diag
__device__ int   g_rowsrc[B * NKEEP];   // source token index per kept output row
__device__ int   g_osrc[B * NOTHER];    // source token index for "other" set
__device__ float g_ow[B * NOTHER];      // softmax weight / NOTHER for "other" set
__device__ int   g_cnt[B];              // per-batch head-completion counter (self-resetting)

// ============================================================
// K1 (fused): column sums minus diagonal per (b,h) plane, float4 streaming.
// grid = B*H = 768 blocks, 512 threads.
// The 12th-completing block per batch runs selection (rank/scan/softmax).
// ============================================================
__global__ __launch_bounds__(512) void colsum_select_kernel(const float* __restrict__ atten) {
    __shared__ float4 s4[4][128];
    __shared__ float  sd[512];
    __shared__ int    s_old;
    __shared__ float v[512];
    __shared__ int   scan[512];
    __shared__ float red[512];

    const int bh = blockIdx.x;
    const int b  = bh / H;
    const int t  = threadIdx.x;
    const float* A = atten + (size_t)bh * S * S;

    // ---- phase 1: plane column-sum (vectorized) ----
    {
        const int q   = t & 127;
        const int seg = t >> 7;
        const float4* A4 = (const float4*)A;
        const float4* Ar = A4 + (size_t)(seg * 128) * S4 + q;

        float4 c0 = make_float4(0.f, 0.f, 0.f, 0.f);
        float4 c1 = make_float4(0.f, 0.f, 0.f, 0.f);
        float4 c2 = make_float4(0.f, 0.f, 0.f, 0.f);
        float4 c3 = make_float4(0.f, 0.f, 0.f, 0.f);
        #pragma unroll 4
        for (int i = 0; i < 128; i += 4) {
            float4 x0 = Ar[(i + 0) * S4];
            float4 x1 = Ar[(i + 1) * S4];
            float4 x2 = Ar[(i + 2) * S4];
            float4 x3 = Ar[(i + 3) * S4];
            c0.x += x0.x; c0.y += x0.y; c0.z += x0.z; c0.w += x0.w;
            c1.x += x1.x; c1.y += x1.y; c1.z += x1.z; c1.w += x1.w;
            c2.x += x2.x; c2.y += x2.y; c2.z += x2.z; c2.w += x2.w;
            c3.x += x3.x; c3.y += x3.y; c3.z += x3.z; c3.w += x3.w;
        }
        float4 cc;
        cc.x = (c0.x + c1.x) + (c2.x + c3.x);
        cc.y = (c0.y + c1.y) + (c2.y + c3.y);
        cc.z = (c0.z + c1.z) + (c2.z + c3.z);
        cc.w = (c0.w + c1.w) + (c2.w + c3.w);
        s4[seg][q] = cc;
        sd[t] = A[(size_t)t * S + t];           // diagonal element j = t
        __syncthreads();

        if (t < 128) {
            float4 a = s4[0][t], bb = s4[1][t], c = s4[2][t], d = s4[3][t];
            float4 tot;
            tot.x = (a.x + bb.x) + (c.x + d.x) - sd[4 * t + 0];
            tot.y = (a.y + bb.y) + (c.y + d.y) - sd[4 * t + 1];
            tot.z = (a.z + bb.z) + (c.z + d.z) - sd[4 * t + 2];
            tot.w = (a.w + bb.w) + (c.w + d.w) - sd[4 * t + 3];
            ((float4*)g_part)[(size_t)bh * 128 + t] = tot;
        }
    }

    // ---- completion handshake ----
    __threadfence();
    if (t == 0) s_old = atomicAdd(&g_cnt[b], 1);
    __syncthreads();
    if (s_old != H - 1) return;
    __threadfence();

    // ---- phase 2: selection for batch b (verbatim from passing kernel) ----
    float val = -3.0e38f;
    if (t < S - 1) {
        float s = 0.f;
        #pragma unroll
        for (int h = 0; h < H; h++)
            s += g_part[(b * H + h) * S + (t + 1)];
        val = s * (1.0f / (float)H);
    }
    v[t] = val;
    __syncthreads();

    int r = 0;
    if (t < S - 1) {
        const float mv = val;
        for (int k = 0; k < S - 1; k++) {
            float vk = v[k];
            r += (vk > mv) || (vk == mv && k < t);
        }
    }
    const int flag = (t < S - 1 && r < TOPK) ? 1 : 0;

    scan[t] = flag;
    __syncthreads();
    for (int off = 1; off < 512; off <<= 1) {
        int x = scan[t];
        int y = (t >= off) ? scan[t - off] : 0;
        __syncthreads();
        scan[t] = x + y;
        __syncthreads();
    }
    const int excl = scan[t] - flag;

    red[t] = (t < S - 1 && !flag) ? val : -3.0e38f;
    __syncthreads();
    for (int off = 256; off > 0; off >>= 1) {
        if (t < off) red[t] = fmaxf(red[t], red[t + off]);
        __syncthreads();
    }
    const float m = red[0];
    __syncthreads();

    const float e = (t < S - 1 && !flag) ? expf(val - m) : 0.f;
    red[t] = e;
    __syncthreads();
    for (int off = 256; off > 0; off >>= 1) {
        if (t < off) red[t] += red[t + off];
        __syncthreads();
    }
    const float Z = red[0];

    if (t < S - 1) {
        if (flag) {
            g_rowsrc[b * NKEEP + 1 + excl] = t + 1;       // slots 1..254, ascending
        } else {
            int p = t - excl;
            g_osrc[b * NOTHER + p] = t + 1;
            g_ow[b * NOTHER + p]   = e / (Z * (float)NOTHER);
        }
    }
    if (t == S - 1) g_rowsrc[b * NKEEP] = 0;              // CLS token
    if (t == 0)     g_cnt[b] = 0;                         // reset for next replay
}

// ============================================================
// K2: output assembly, flat grid, 768 threads.
//   blocks 0..63         : weighted-mean row for batch b = blockIdx.x
//                          (4 row-groups x 192 cols, smem cross-group reduce)
//   blocks 64..64+4079   : pure memcpy-shaped copy, exactly 1 float4/thread
// ============================================================
__global__ __launch_bounds__(GATHER_THREADS) void gather_kernel(const float4* __restrict__ x4,
                                                                float4* __restrict__ out4) {
    const int t = threadIdx.x;

    if (blockIdx.x < B) {
        // ---- weighted mean of the 257 "other" rows for batch b ----
        const int b = blockIdx.x;
        const float4* xb = x4 + (size_t)b * S * D4;

        __shared__ float  sw[NOTHER];
        __shared__ int    ss[NOTHER];
        __shared__ float4 sred[4][D4];

        if (t < NOTHER) {
            sw[t] = g_ow[b * NOTHER + t];
            ss[t] = g_osrc[b * NOTHER + t];
        }
        __syncthreads();

        const int g = t / D4;        // row group 0..3
        const int c = t % D4;        // column (float4)
        float4 acc = make_float4(0.f, 0.f, 0.f, 0.f);
        #pragma unroll 4
        for (int q = g; q < NOTHER; q += 4) {
            const float  w  = sw[q];
            const float4 xv = xb[ss[q] * D4 + c];
            acc.x += w * xv.x;
            acc.y += w * xv.y;
            acc.z += w * xv.z;
            acc.w += w * xv.w;
        }
        sred[g][c] = acc;
        __syncthreads();

        if (t < D4) {
            float4 a0 = sred[0][t], a1 = sred[1][t], a2 = sred[2][t], a3 = sred[3][t];
            float4 tot;
            tot.x = (a0.x + a1.x) + (a2.x + a3.x);
            tot.y = (a0.y + a1.y) + (a2.y + a3.y);
            tot.z = (a0.z + a1.z) + (a2.z + a3.z);
            tot.w = (a0.w + a1.w) + (a2.w + a3.w);
            out4[((size_t)b * 256 + 255) * D4 + t] = tot;
        }
    } else {
        // ---- copy kept rows: one float4 per thread ----
        const int e   = (blockIdx.x - B) * GATHER_THREADS + t;   // < NCOPY_ELEM
        const int b   = e / (NKEEP * D4);
        const int rem = e - b * (NKEEP * D4);
        const int row = rem / D4;
        const int col = rem - row * D4;
        const int src = __ldg(&g_rowsrc[b * NKEEP + row]);
        out4[((size_t)b * 256 + row) * D4 + col] = x4[((size_t)b * S + src) * D4 + col];
    }
}

extern "C" void kernel_launch(void* const* d_in, const int* in_sizes, int n_in,
                              void* d_out, int out_size) {
    const float* x     = (const float*)d_in[0];   // (64, 512, 768) f32
    const float* atten = (const float*)d_in[1];   // (768, 512, 512) f32
    // d_in[2] = index (int32, == 256) -- baked into compile-time constants

    colsum_select_kernel<<<B * H, 512>>>(atten);
    gather_kernel<<<B + NCOPY_BLOCKS, GATHER_THREADS>>>((const float4*)x, (float4*)d_out);
}